// round 12
// baseline (speedup 1.0000x reference)
#include <cuda_runtime.h>
#include <cuda_bf16.h>
#include <cstdint>

// Problem constants.
#define D    96      // D_IN == D_OUT
#define K2   192     // concat K = 2*D
#define MAXN 50000
#define MAXE 800000

// Scratch (no cudaMalloc allowed). uint4 typing guarantees 16B alignment.
__device__ float g_agg[(size_t)MAXN * D];        // neighbor MEAN (written densely)
__device__ int   g_count[MAXN];                  // per-dst edge count
__device__ int   g_rowptr[MAXN + 1];             // CSR row pointers
__device__ int   g_cursor[MAXN];                 // placement cursors
__device__ int   g_srcs[MAXE];                   // src ids grouped by dst
__device__ uint4 g_Bhi4[(D * K2 * 2) / 16];      // [96][192] bf16 Wcat hi
__device__ uint4 g_Blo4[(D * K2 * 2) / 16];      // [96][192] bf16 Wcat lo

// ---------------------------------------------------------------------------
// helpers
// ---------------------------------------------------------------------------
__device__ __forceinline__ uint32_t smem_u32(const void* p) {
    uint32_t a;
    asm("{ .reg .u64 t; cvta.to.shared.u64 t, %1; cvt.u32.u64 %0, t; }"
        : "=r"(a) : "l"(p));
    return a;
}

__device__ __forceinline__ uint32_t pack_bf16x2(float a, float b) {
    uint32_t r;
    asm("cvt.rn.bf16x2.f32 %0, %1, %2;" : "=r"(r) : "f"(b), "f"(a));
    return r;
}

#define LDSM_X4(r, addr)                                                      \
    asm volatile("ldmatrix.sync.aligned.m8n8.x4.shared.b16 "                  \
                 "{%0,%1,%2,%3}, [%4];"                                       \
                 : "=r"((r)[0]), "=r"((r)[1]), "=r"((r)[2]), "=r"((r)[3])     \
                 : "r"(addr))

__device__ __forceinline__ void mma_bf16(float* c, const uint32_t* a,
                                         uint32_t b0, uint32_t b1) {
    asm volatile(
        "mma.sync.aligned.m16n8k16.row.col.f32.bf16.bf16.f32 "
        "{%0,%1,%2,%3}, {%4,%5,%6,%7}, {%8,%9}, {%0,%1,%2,%3};"
        : "+f"(c[0]), "+f"(c[1]), "+f"(c[2]), "+f"(c[3])
        : "r"(a[0]), "r"(a[1]), "r"(a[2]), "r"(a[3]), "r"(b0), "r"(b1));
}

// ---------------------------------------------------------------------------
// 0) prep: zero counts + split W = [Wl|Wr] into bf16 hi/lo
// ---------------------------------------------------------------------------
__global__ void prep_kernel(const float* __restrict__ Wl,
                            const float* __restrict__ Wr, int n)
{
    int idx = blockIdx.x * blockDim.x + threadIdx.x;
    int stride = gridDim.x * blockDim.x;
    for (int i = idx; i < n; i += stride) g_count[i] = 0;
    for (int i = idx; i < D * K2; i += stride) {
        int r = i / K2, k = i % K2;
        float w = (k < D) ? Wl[r * D + k] : Wr[r * D + (k - D)];
        __nv_bfloat16 h = __float2bfloat16(w);
        reinterpret_cast<__nv_bfloat16*>(g_Bhi4)[i] = h;
        reinterpret_cast<__nv_bfloat16*>(g_Blo4)[i] =
            __float2bfloat16(w - __bfloat162float(h));
    }
}

// ---------------------------------------------------------------------------
// 1) histogram of dst (4 independent RED chains per thread)
// ---------------------------------------------------------------------------
__global__ void hist_kernel(const int* __restrict__ ei, int E) {
    int i = blockIdx.x * blockDim.x + threadIdx.x;
    int Q = gridDim.x * blockDim.x;
    int e0 = i, e1 = i + Q, e2 = i + 2 * Q, e3 = i + 3 * Q;
    if (e0 < E) atomicAdd(&g_count[__ldg(ei + E + e0)], 1);
    if (e1 < E) atomicAdd(&g_count[__ldg(ei + E + e1)], 1);
    if (e2 < E) atomicAdd(&g_count[__ldg(ei + E + e2)], 1);
    if (e3 < E) atomicAdd(&g_count[__ldg(ei + E + e3)], 1);
}

// ---------------------------------------------------------------------------
// 2) exclusive scan (single block, 1024 threads, shfl two-level)
// ---------------------------------------------------------------------------
__global__ __launch_bounds__(1024) void scan_kernel(int n) {
    __shared__ int warpsum[32];
    int tid = threadIdx.x, lane = tid & 31, w = tid >> 5;
    int seg = (n + 1023) >> 10;
    int start = min(tid * seg, n);
    int end = min(start + seg, n);

    int s = 0;
    for (int i = start; i < end; ++i) s += g_count[i];

    int v = s;
#pragma unroll
    for (int o = 1; o < 32; o <<= 1) {
        int t = __shfl_up_sync(0xffffffffu, v, o);
        if (lane >= o) v += t;
    }
    if (lane == 31) warpsum[w] = v;
    __syncthreads();
    if (w == 0) {
        int ws = warpsum[lane];
#pragma unroll
        for (int o = 1; o < 32; o <<= 1) {
            int t = __shfl_up_sync(0xffffffffu, ws, o);
            if (lane >= o) ws += t;
        }
        warpsum[lane] = ws;
    }
    __syncthreads();

    int base = (w > 0) ? warpsum[w - 1] : 0;
    int run = base + v - s;
    for (int i = start; i < end; ++i) {
        int c = g_count[i];
        g_rowptr[i] = run;
        g_cursor[i] = run;
        run += c;
    }
    if (end == n) g_rowptr[n] = run;
}

// ---------------------------------------------------------------------------
// 3) place edges (4 independent atomic chains per thread)
// ---------------------------------------------------------------------------
__global__ void place_kernel(const int* __restrict__ ei, int E) {
    int i = blockIdx.x * blockDim.x + threadIdx.x;
    int Q = gridDim.x * blockDim.x;
#pragma unroll
    for (int u = 0; u < 4; ++u) {
        int e = i + u * Q;
        if (e < E) {
            int src = __ldg(ei + e);
            int dst = __ldg(ei + E + e);
            int p = atomicAdd(&g_cursor[dst], 1);
            g_srcs[p] = src;
        }
    }
}

// ---------------------------------------------------------------------------
// 4) gather-mean: warp-per-node, g_agg[node] = mean of x[src] over in-edges
// ---------------------------------------------------------------------------
__global__ __launch_bounds__(256) void gather_kernel(
    const float* __restrict__ x, int N)
{
    int node = blockIdx.x * 8 + (threadIdx.x >> 5);
    if (node >= N) return;
    int lane = threadIdx.x & 31;
    bool act = lane < 24;
    int c = lane;                         // float4 chunk 0..23

    int rp0 = __ldg(g_rowptr + node);
    int rp1 = __ldg(g_rowptr + node + 1);

    float4 a0 = make_float4(0.f, 0.f, 0.f, 0.f);
    float4 a1 = make_float4(0.f, 0.f, 0.f, 0.f);
    float4 a2 = make_float4(0.f, 0.f, 0.f, 0.f);
    float4 a3 = make_float4(0.f, 0.f, 0.f, 0.f);

    int e = rp0;
    for (; e + 4 <= rp1; e += 4) {
        int s0 = __ldg(g_srcs + e);
        int s1 = __ldg(g_srcs + e + 1);
        int s2 = __ldg(g_srcs + e + 2);
        int s3 = __ldg(g_srcs + e + 3);
        if (act) {
            float4 v0 = __ldg(reinterpret_cast<const float4*>(x + (size_t)s0 * D) + c);
            float4 v1 = __ldg(reinterpret_cast<const float4*>(x + (size_t)s1 * D) + c);
            float4 v2 = __ldg(reinterpret_cast<const float4*>(x + (size_t)s2 * D) + c);
            float4 v3 = __ldg(reinterpret_cast<const float4*>(x + (size_t)s3 * D) + c);
            a0.x += v0.x; a0.y += v0.y; a0.z += v0.z; a0.w += v0.w;
            a1.x += v1.x; a1.y += v1.y; a1.z += v1.z; a1.w += v1.w;
            a2.x += v2.x; a2.y += v2.y; a2.z += v2.z; a2.w += v2.w;
            a3.x += v3.x; a3.y += v3.y; a3.z += v3.z; a3.w += v3.w;
        }
    }
    for (; e < rp1; ++e) {
        int s0 = __ldg(g_srcs + e);
        if (act) {
            float4 v0 = __ldg(reinterpret_cast<const float4*>(x + (size_t)s0 * D) + c);
            a0.x += v0.x; a0.y += v0.y; a0.z += v0.z; a0.w += v0.w;
        }
    }

    if (act) {
        float inv = 1.0f / fmaxf((float)(rp1 - rp0), 1.0f);
        float4 o;
        o.x = ((a0.x + a1.x) + (a2.x + a3.x)) * inv;
        o.y = ((a0.y + a1.y) + (a2.y + a3.y)) * inv;
        o.z = ((a0.z + a1.z) + (a2.z + a3.z)) * inv;
        o.w = ((a0.w + a1.w) + (a2.w + a3.w)) * inv;
        *(reinterpret_cast<float4*>(g_agg + (size_t)node * D) + c) = o;
    }
}

// ---------------------------------------------------------------------------
// 5) GEMM: out = relu([mean | x] @ [Wl|Wr]^T + bl)   (R8 design, deg removed)
// ---------------------------------------------------------------------------
#define BRS 384
#define SM_BLO_OFF (96 * BRS)
#define SM_TOTAL (2 * 96 * BRS)      // 73728 B

__device__ __forceinline__ int bswz(int row, int chunk) {
    return ((chunk & ~7) | ((chunk ^ row) & 7)) << 4;
}

__global__ __launch_bounds__(256, 2) void fused_gemm_kernel(
    const float* __restrict__ x, const float* __restrict__ bl,
    float* __restrict__ out, int N)
{
    extern __shared__ char smem[];

    const int tid  = threadIdx.x;
    const int wid  = tid >> 5;
    const int lane = tid & 31;
    const int m0   = blockIdx.x * 128;
    const int mbase = m0 + wid * 16;

    for (int l = tid; l < 2304; l += 256) {
        int n = l / 24, q = l % 24;
        int so = n * BRS + bswz(n, q);
        *reinterpret_cast<uint4*>(smem + so) = g_Bhi4[l];
        *reinterpret_cast<uint4*>(smem + SM_BLO_OFF + so) = g_Blo4[l];
    }

    const int g = lane >> 2, t = lane & 3;
    const int r0 = mbase + g, r1 = r0 + 8;
    const bool ok0 = r0 < N, ok1 = r1 < N;
    const float* aggp0 = g_agg + (size_t)(ok0 ? r0 : 0) * D;
    const float* aggp1 = g_agg + (size_t)(ok1 ? r1 : 0) * D;
    const float* xp0   = x     + (size_t)(ok0 ? r0 : 0) * D;
    const float* xp1   = x     + (size_t)(ok1 ? r1 : 0) * D;

    const int lrow8  = lane & 7;
    const int brow   = lrow8 + ((lane >> 4) << 3);
    const int bksel  = (lane >> 3) & 1;
    const uint32_t sb = smem_u32(smem);

    float acc[12][4];
#pragma unroll
    for (int j = 0; j < 12; ++j)
#pragma unroll
        for (int r = 0; r < 4; ++r) acc[j][r] = 0.f;

    auto load_raw = [&](int ks, float2* v) {
        const float2 z = make_float2(0.f, 0.f);
        const int col = (ks < 6) ? ks * 16 + 2 * t : (ks - 6) * 16 + 2 * t;
        const float* p0 = (ks < 6) ? aggp0 : xp0;
        const float* p1 = (ks < 6) ? aggp1 : xp1;
        v[0] = ok0 ? __ldg(reinterpret_cast<const float2*>(p0 + col))     : z;
        v[1] = ok0 ? __ldg(reinterpret_cast<const float2*>(p0 + col + 8)) : z;
        v[2] = ok1 ? __ldg(reinterpret_cast<const float2*>(p1 + col))     : z;
        v[3] = ok1 ? __ldg(reinterpret_cast<const float2*>(p1 + col + 8)) : z;
    };

    __syncthreads();

    float2 raw[4];
    load_raw(0, raw);

#pragma unroll
    for (int ks = 0; ks < 12; ++ks) {
        float2 nxt[4];
        if (ks < 11) load_raw(ks + 1, nxt);

        float vx[4][2] = {{raw[0].x, raw[0].y},
                          {raw[2].x, raw[2].y},
                          {raw[1].x, raw[1].y},
                          {raw[3].x, raw[3].y}};
        uint32_t ahi[4], alo[4];
#pragma unroll
        for (int i = 0; i < 4; ++i) {
            ahi[i] = pack_bf16x2(vx[i][0], vx[i][1]);
            alo[i] = pack_bf16x2(vx[i][0] - __uint_as_float(ahi[i] << 16),
                                 vx[i][1] - __uint_as_float(ahi[i] & 0xffff0000u));
        }

        const int ch = 2 * ks + bksel;
        const uint32_t bOff = brow * BRS + bswz(lrow8, ch);

        uint32_t b[6][4];
#pragma unroll
        for (int q = 0; q < 6; ++q)
            LDSM_X4(b[q], sb + bOff + q * 16 * BRS);
#pragma unroll
        for (int j = 0; j < 12; ++j)
            mma_bf16(acc[j], ahi, b[j >> 1][(j & 1) * 2], b[j >> 1][(j & 1) * 2 + 1]);
#pragma unroll
        for (int j = 0; j < 12; ++j)
            mma_bf16(acc[j], alo, b[j >> 1][(j & 1) * 2], b[j >> 1][(j & 1) * 2 + 1]);

#pragma unroll
        for (int q = 0; q < 6; ++q)
            LDSM_X4(b[q], sb + SM_BLO_OFF + bOff + q * 16 * BRS);
#pragma unroll
        for (int j = 0; j < 12; ++j)
            mma_bf16(acc[j], ahi, b[j >> 1][(j & 1) * 2], b[j >> 1][(j & 1) * 2 + 1]);

#pragma unroll
        for (int i = 0; i < 4; ++i) raw[i] = nxt[i];
    }

    const int erow = lane >> 2;
    const int ecol = (lane & 3) * 2;
#pragma unroll
    for (int j = 0; j < 12; ++j) {
        int col = j * 8 + ecol;
        float b0 = __ldg(bl + col);
        float b1 = __ldg(bl + col + 1);
        int row0 = mbase + erow;
        if (row0 < N) {
            float2 o = make_float2(fmaxf(acc[j][0] + b0, 0.f),
                                   fmaxf(acc[j][1] + b1, 0.f));
            *reinterpret_cast<float2*>(out + (size_t)row0 * D + col) = o;
        }
        int row1 = row0 + 8;
        if (row1 < N) {
            float2 o = make_float2(fmaxf(acc[j][2] + b0, 0.f),
                                   fmaxf(acc[j][3] + b1, 0.f));
            *reinterpret_cast<float2*>(out + (size_t)row1 * D + col) = o;
        }
    }
}

// ---------------------------------------------------------------------------
// kernel_launch
// ---------------------------------------------------------------------------
extern "C" void kernel_launch(void* const* d_in, const int* in_sizes, int n_in,
                              void* d_out, int out_size)
{
    const float* x  = (const float*)d_in[0];
    const int*   ei = (const int*)  d_in[1];
    const float* Wl = (const float*)d_in[2];
    const float* bl = (const float*)d_in[3];
    const float* Wr = (const float*)d_in[4];
    float* out = (float*)d_out;

    const int N = in_sizes[0] / D;
    const int E = in_sizes[1] / 2;

    cudaFuncSetAttribute(fused_gemm_kernel,
                         cudaFuncAttributeMaxDynamicSharedMemorySize, SM_TOTAL);

    int prep_elems = (N > D * K2) ? N : D * K2;
    prep_kernel<<<(prep_elems + 255) / 256, 256>>>(Wl, Wr, N);

    int qblocks = (E / 4 + 255) / 256;              // 4 edges per thread
    hist_kernel<<<qblocks, 256>>>(ei, E);
    scan_kernel<<<1, 1024>>>(N);
    place_kernel<<<qblocks, 256>>>(ei, E);

    gather_kernel<<<(N + 7) / 8, 256>>>(x, N);

    fused_gemm_kernel<<<(N + 127) / 128, 256, SM_TOTAL>>>(x, bl, out, N);
}